// round 3
// baseline (speedup 1.0000x reference)
#include <cuda_runtime.h>
#include <math.h>

#define Bb 4
#define Nn 5
#define Kk 5
#define Ll 128
#define Ff 768
#define NQc 25
#define BQ 100
#define ROWS (Kk*Ll)         // 640 rows per (b,n)
#define EPSc 1e-8f

// ---------------- scratch -------------------------------------------------
__device__ float g_proto[Bb*Nn*4*Ff];    // finalized (divided) prototypes
__device__ float g_sproto[Bb*Nn*Ff];     // sentence prototypes
__device__ int   g_spred[BQ];
__device__ float g_bce[BQ];
__device__ unsigned long long g_amax[BQ*4];

__device__ __forceinline__ float dot4(float4 a, float4 b) {
    return a.x*b.x + a.y*b.y + a.z*b.z + a.w*b.w;
}
__device__ __forceinline__ unsigned long long enc_key(float v, int l) {
    unsigned u = __float_as_uint(v);
    u = (u & 0x80000000u) ? ~u : (u | 0x80000000u);
    return ((unsigned long long)u << 32) | (unsigned long long)(0xFFFFFFFFu - (unsigned)l);
}

// ============ K1: prototypes (atomic-free) + sentence protos + zeroing =====
// grid (12 f-chunks, 20 bn), 256 threads. Thread t: r = t>>6 row-phase, f = t&63.
__global__ void k_proto(const float* __restrict__ sup,
                        const int* __restrict__ sem,
                        const int* __restrict__ sam,
                        float* __restrict__ out) {
    int fc  = blockIdx.x;           // 0..11
    int bn  = blockIdx.y;           // 0..19
    int tid = threadIdx.x;
    int r   = tid >> 6;             // 0..3
    int f   = tid & 63;
    int gf  = fc*64 + f;

    __shared__ int slab[ROWS];
    __shared__ int sden[4];
    if (tid < 4) sden[tid] = 0;
    __syncthreads();

    int c0=0,c1=0,c2=0,c3=0;
    for (int i = tid; i < ROWS; i += 256) {
        int lab = sem[bn*ROWS + i];
        int att = sam[bn*ROWS + i];
        int c = (att > 0 && lab >= 1 && lab <= 4) ? (lab-1) : -1;
        slab[i] = c;
        if      (c==0) c0++; else if (c==1) c1++;
        else if (c==2) c2++; else if (c==3) c3++;
    }
    if (c0) atomicAdd(&sden[0], c0);
    if (c1) atomicAdd(&sden[1], c1);
    if (c2) atomicAdd(&sden[2], c2);
    if (c3) atomicAdd(&sden[3], c3);
    __syncthreads();

    float a0=0,a1=0,a2=0,a3=0, sa=0;
    const float* base = sup + (size_t)bn*ROWS*Ff + gf;
    #pragma unroll 4
    for (int row0 = 0; row0 < ROWS; row0 += 4) {
        int row = row0 + r;
        int c = slab[row];
        bool sent = ((row & (Ll-1)) == 0);
        if (c < 0 && !sent) continue;        // skip unlabeled rows
        float v = base[(size_t)row*Ff];
        if (sent) sa += v;
        if      (c==0) a0+=v; else if (c==1) a1+=v;
        else if (c==2) a2+=v; else if (c==3) a3+=v;
    }

    __shared__ float smA[4][4][64];          // [class][r][f]
    __shared__ float smS[4][64];
    smA[0][r][f]=a0; smA[1][r][f]=a1; smA[2][r][f]=a2; smA[3][r][f]=a3;
    smS[r][f]=sa;
    __syncthreads();
    if (r == 0) {
        #pragma unroll
        for (int c = 0; c < 4; c++) {
            float t = smA[c][0][f]+smA[c][1][f]+smA[c][2][f]+smA[c][3][f];
            g_proto[((size_t)(bn*4+c))*Ff + gf] = t / ((float)sden[c] + EPSc);
        }
        float ts = smS[0][f]+smS[1][f]+smS[2][f]+smS[3][f];
        g_sproto[(size_t)bn*Ff + gf] = ts * (1.f/Kk);
    }

    if (fc == 0 && bn == 0) {                // zero scratch for K2/K3
        for (int i = tid; i < BQ;   i += 256) g_bce[i]  = 0.f;
        for (int i = tid; i < BQ*4; i += 256) g_amax[i] = 0ull;
        if (tid == 0) out[0] = 0.f;
    }
}

// ============ K2: token logits + BCE + argmax  (+ sentence loss fused) =====
// grid (BQ, 16), 256 threads = 8 warps; warp w handles l = by*8 + w
__global__ void k_main(const float* __restrict__ qemb,
                       const int* __restrict__ qem,
                       const int* __restrict__ qatt_in,
                       const int* __restrict__ slabel,
                       float* __restrict__ out) {
    int bq   = blockIdx.x;
    int b    = bq / NQc;
    int tid  = threadIdx.x;
    int w    = tid >> 5;
    int lane = tid & 31;
    int l    = blockIdx.y * 8 + w;
    int cond = slabel[bq];

    __shared__ float sp[4*Ff];               // 12 KB
    __shared__ float sp2[4];
    __shared__ float sred[256];
    __shared__ float sdist[Nn];
    const float* pb = g_proto + (size_t)(b*Nn + cond) * 4 * Ff;
    for (int i = tid; i < 4*Ff; i += 256) sp[i] = pb[i];
    __syncthreads();

    // p2 per class: warps 0-3, one class each, shuffle reduce
    if (w < 4) {
        float s = 0.f;
        #pragma unroll
        for (int k = 0; k < Ff/32; k++) {
            float p = sp[w*Ff + lane + k*32];
            s += p*p;
        }
        #pragma unroll
        for (int off = 16; off; off >>= 1) s += __shfl_xor_sync(0xffffffffu, s, off);
        if (lane == 0) sp2[w] = s;
    }
    __syncthreads();

    const float4* q4  = (const float4*)(qemb + ((size_t)bq * Ll + l) * Ff);
    const float4* p0  = (const float4*)(sp + 0*Ff);
    const float4* p1  = (const float4*)(sp + 1*Ff);
    const float4* p2v = (const float4*)(sp + 2*Ff);
    const float4* p3  = (const float4*)(sp + 3*Ff);

    float q2 = 0.f, s0 = 0.f, s1 = 0.f, s2 = 0.f, s3 = 0.f;
    #pragma unroll
    for (int j = 0; j < 6; j++) {
        float4 qv = q4[lane + j*32];
        q2 += dot4(qv, qv);
        s0 += dot4(qv, p0[lane + j*32]);
        s1 += dot4(qv, p1[lane + j*32]);
        s2 += dot4(qv, p2v[lane + j*32]);
        s3 += dot4(qv, p3[lane + j*32]);
    }
    #pragma unroll
    for (int off = 16; off; off >>= 1) {
        q2 += __shfl_xor_sync(0xffffffffu, q2, off);
        s0 += __shfl_xor_sync(0xffffffffu, s0, off);
        s1 += __shfl_xor_sync(0xffffffffu, s1, off);
        s2 += __shfl_xor_sync(0xffffffffu, s2, off);
        s3 += __shfl_xor_sync(0xffffffffu, s3, off);
    }

    __shared__ float sbce[8];
    __shared__ unsigned long long skey[8][4];
    if (lane == 0) {
        float qatt = (float)qatt_in[bq*Ll + l];
        int   tlab = qem[bq*Ll + l];
        float qp[4] = { s0, s1, s2, s3 };
        float bcesum = 0.f;
        #pragma unroll
        for (int c = 0; c < 4; c++) {
            float x = -(q2 + sp2[c] - 2.f * qp[c]);
            float t = (tlab == c + 1) ? 1.f : 0.f;
            bcesum += fmaxf(x, 0.f) - x * t + log1pf(expf(-fabsf(x)));
            float m = x - 1000.f * (1.f - qatt);
            skey[w][c] = enc_key(m, l);
        }
        sbce[w] = bcesum * qatt;
    }
    __syncthreads();
    if (tid < 4) {
        unsigned long long mk = skey[0][tid];
        #pragma unroll
        for (int i = 1; i < 8; i++) if (skey[i][tid] > mk) mk = skey[i][tid];
        atomicMax(&g_amax[bq*4 + tid], mk);
    }
    if (tid == 0) {
        float s = 0.f;
        #pragma unroll
        for (int i = 0; i < 8; i++) s += sbce[i];
        atomicAdd(&g_bce[bq], s);
    }

    // -------- fused sentence path (one block-row per bq) --------
    if (blockIdx.y == 0) {
        __syncthreads();
        float dpart[Nn] = {0.f,0.f,0.f,0.f,0.f};
        const float* qrow = qemb + (size_t)bq * Ll * Ff;   // l = 0 slice
        #pragma unroll
        for (int j = 0; j < 3; j++) {
            float qv = qrow[tid + j*256];
            #pragma unroll
            for (int n = 0; n < Nn; n++) {
                float dd = g_sproto[(b*Nn + n)*Ff + tid + j*256] - qv;
                dpart[n] += dd * dd;
            }
        }
        for (int n = 0; n < Nn; n++) {
            sred[tid] = dpart[n]; __syncthreads();
            for (int s = 128; s > 0; s >>= 1) {
                if (tid < s) sred[tid] += sred[tid + s];
                __syncthreads();
            }
            if (tid == 0) sdist[n] = sred[0];
            __syncthreads();
        }
        if (tid == 0) {
            float lg[Nn];
            float mx = -1e30f;
            int pred = 0;
            #pragma unroll
            for (int n = 0; n < Nn; n++) {
                lg[n] = -sdist[n];
                if (lg[n] > mx) { mx = lg[n]; pred = n; }
            }
            float se = 0.f;
            #pragma unroll
            for (int n = 0; n < Nn; n++) se += expf(lg[n] - mx);
            float lse = mx + logf(se);
            int lab = slabel[bq];
            atomicAdd(out, -(lg[lab] - lse) * (1.f / BQ));
            g_spred[bq] = pred;
        }
    }
}

// ============ K3: final_pred + token-loss accumulation =====================
__global__ void k_finpred(const int* __restrict__ qatt_in,
                          float* __restrict__ out) {
    int bq = blockIdx.x;
    int l  = threadIdx.x;                    // 128
    float qatt = (float)qatt_in[bq*Ll + l];

    __shared__ float red[128];
    red[l] = qatt; __syncthreads();
    for (int s = 64; s > 0; s >>= 1) {
        if (l < s) red[l] += red[l + s];
        __syncthreads();
    }
    __shared__ int si[4];
    if (l < 4)
        si[l] = (int)(0xFFFFFFFFu - (unsigned)(g_amax[bq*4 + l] & 0xFFFFFFFFull));
    if (l == 0)
        atomicAdd(out, g_bce[bq] / (red[0] * 4.f + EPSc) * (1.f / BQ));
    __syncthreads();

    int i0 = si[0], i1 = si[1], i2 = si[2], i3 = si[3];
    int p = 0;
    if (l == i0)            p = 1;
    if (l > i0 && l <= i1)  p = 2;
    if (l == i2)            p = 3;
    if (l > i2 && l <= i3)  p = 4;
    int sp = g_spred[bq];
    out[1 + bq*Ll + l] = (float)((p != 0) ? (4*sp + p) : 0);
}

// ---------------- launch ----------------------------------------------------
extern "C" void kernel_launch(void* const* d_in, const int* in_sizes, int n_in,
                              void* d_out, int out_size) {
    const float* sup    = (const float*)d_in[0];
    const float* qemb   = (const float*)d_in[1];
    const int*   sem    = (const int*)d_in[2];
    const int*   qem    = (const int*)d_in[3];
    const int*   sam    = (const int*)d_in[4];
    const int*   qatt   = (const int*)d_in[5];
    const int*   slabel = (const int*)d_in[6];
    float* out = (float*)d_out;

    {
        dim3 g(12, 20);
        k_proto<<<g, 256>>>(sup, sem, sam, out);
    }
    {
        dim3 g(BQ, 16);
        k_main<<<g, 256>>>(qemb, qem, qatt, slabel, out);
    }
    k_finpred<<<BQ, 128>>>(qatt, out);
}